// round 2
// baseline (speedup 1.0000x reference)
#include <cuda_runtime.h>
#include <math.h>

#define BB 128
#define TT 512
#define DD 1024
#define HH 1024
#define NGATE 4096   // 4*H
#define NCTA 128     // persistent grid size (<=148 SMs -> all co-resident)

// Scratch (static device globals — no runtime allocation).
__device__ float g_xg[(size_t)TT * BB * NGATE];        // [t][b][4H] input projections
__device__ float g_part[4 * BB * NGATE];               // split-K partials [ks][b][4H]
__device__ float g_h[BB * HH];                         // recurrent h
__device__ unsigned g_bar;                             // grid barrier counter (never reset)

// ---------------------------------------------------------------------------
// GEMM1: xg[t][b][n] = sum_k x[b][t][k] * Wx[g][k][h]   (n = g*1024+h)
// Tile 128x128x16, 256 threads, 8x8 per thread. grid = (32 n-tiles, 512 t).
// ---------------------------------------------------------------------------
__global__ __launch_bounds__(256) void gemm_xgates(
    const float* __restrict__ x, const float* __restrict__ Wx,
    float* __restrict__ out)
{
    __shared__ float As[16][128];   // [k][m]
    __shared__ float Bs[16][128];   // [k][n]

    const int tid = threadIdx.x;
    const int t  = blockIdx.y;
    const int n0 = blockIdx.x * 128;
    const int g  = n0 >> 10;
    const int hb = n0 & 1023;

    const int ar = tid >> 2;          // 0..63
    const int ac = (tid & 3) << 2;    // 0,4,8,12
    const int br = tid >> 5;          // 0..7
    const int bc = (tid & 31) << 2;   // 0..124

    const int tx = tid & 15;
    const int ty = tid >> 4;

    float acc[8][8];
#pragma unroll
    for (int i = 0; i < 8; i++)
#pragma unroll
        for (int j = 0; j < 8; j++) acc[i][j] = 0.f;

    const float* Wg = Wx + (size_t)g * DD * HH + hb;

    for (int kt = 0; kt < DD; kt += 16) {
#pragma unroll
        for (int rr = 0; rr < 2; rr++) {
            int r = ar + rr * 64;     // r == b
            float4 v = *(const float4*)(x + (size_t)r * (TT * DD) + (size_t)t * DD + kt + ac);
            As[ac + 0][r] = v.x; As[ac + 1][r] = v.y;
            As[ac + 2][r] = v.z; As[ac + 3][r] = v.w;
        }
#pragma unroll
        for (int rr = 0; rr < 2; rr++) {
            int r = br + rr * 8;
            *(float4*)&Bs[r][bc] = *(const float4*)(Wg + (size_t)(kt + r) * HH + bc);
        }
        __syncthreads();
#pragma unroll
        for (int kk = 0; kk < 16; kk++) {
            float a[8], bfr[8];
            *(float4*)&a[0]   = *(float4*)&As[kk][ty * 4];
            *(float4*)&a[4]   = *(float4*)&As[kk][64 + ty * 4];
            *(float4*)&bfr[0] = *(float4*)&Bs[kk][tx * 4];
            *(float4*)&bfr[4] = *(float4*)&Bs[kk][64 + tx * 4];
#pragma unroll
            for (int i = 0; i < 8; i++)
#pragma unroll
                for (int j = 0; j < 8; j++)
                    acc[i][j] = fmaf(a[i], bfr[j], acc[i][j]);
        }
        __syncthreads();
    }

#pragma unroll
    for (int i = 0; i < 8; i++) {
        int m = (i < 4) ? (ty * 4 + i) : (64 + ty * 4 + (i - 4));
        float* cp = out + ((size_t)t * BB + m) * NGATE + n0;
        *(float4*)(cp + tx * 4)      = make_float4(acc[i][0], acc[i][1], acc[i][2], acc[i][3]);
        *(float4*)(cp + 64 + tx * 4) = make_float4(acc[i][4], acc[i][5], acc[i][6], acc[i][7]);
    }
}

// ---------------------------------------------------------------------------
// Grid barrier: stateless generation counter (safe across graph replays;
// counter is always a multiple of NCTA between launches).
// ---------------------------------------------------------------------------
__device__ __forceinline__ void grid_barrier()
{
    __syncthreads();
    if (threadIdx.x == 0) {
        __threadfence();
        unsigned old = atomicAdd(&g_bar, 1u);
        unsigned target = (old / NCTA + 1u) * (unsigned)NCTA;
        while (atomicAdd(&g_bar, 0u) < target) { __nanosleep(32); }
        __threadfence();
    }
    __syncthreads();
}

// ---------------------------------------------------------------------------
// Persistent recurrence: 128 CTAs x 256 threads, 512 steps.
// Each step: split-K GEMM partial (CTA = (n-tile, ksplit)) -> barrier ->
// fused LSTM activation (CTA b owns batch-row b; c lives in registers) ->
// barrier.
// ---------------------------------------------------------------------------
__global__ __launch_bounds__(256) void lstm_recurrence(
    const float* __restrict__ Wh, const float* __restrict__ xg,
    const float* __restrict__ bias, float* __restrict__ out)
{
    __shared__ float As[16][128];
    __shared__ float Bs[16][128];

    const int tid = threadIdx.x;
    const int nt = blockIdx.x & 31;     // n-tile 0..31
    const int ks = blockIdx.x >> 5;     // k-split 0..3
    const int n0 = nt * 128;
    const int g  = n0 >> 10;
    const int hb = n0 & 1023;
    const int k0 = ks * 256;

    const int ar = tid >> 2;
    const int ac = (tid & 3) << 2;
    const int br = tid >> 5;
    const int bc = (tid & 31) << 2;
    const int tx = tid & 15;
    const int ty = tid >> 4;

    const float* Wg = Wh + (size_t)g * HH * HH + hb;

    // Activation role: this CTA owns batch row b = blockIdx.x, cols tid*4..+3.
    const int bown = blockIdx.x;
    const int hcol = tid * 4;
    float4 creg = make_float4(0.f, 0.f, 0.f, 0.f);
    float4 b0 = *(const float4*)(bias + hcol);
    float4 b1 = *(const float4*)(bias + 1024 + hcol);
    float4 b2 = *(const float4*)(bias + 2048 + hcol);
    float4 b3 = *(const float4*)(bias + 3072 + hcol);

    // h := 0
    *(float4*)(g_h + bown * HH + hcol) = make_float4(0.f, 0.f, 0.f, 0.f);
    grid_barrier();

    for (int t = 0; t < TT; t++) {
        // ---- GEMM partial: part[ks][b][n0..n0+127] over k in [k0,k0+256) ----
        float acc[8][8];
#pragma unroll
        for (int i = 0; i < 8; i++)
#pragma unroll
            for (int j = 0; j < 8; j++) acc[i][j] = 0.f;

        for (int kt = k0; kt < k0 + 256; kt += 16) {
#pragma unroll
            for (int rr = 0; rr < 2; rr++) {
                int r = ar + rr * 64;
                float4 v = *(const float4*)(g_h + (size_t)r * HH + kt + ac);
                As[ac + 0][r] = v.x; As[ac + 1][r] = v.y;
                As[ac + 2][r] = v.z; As[ac + 3][r] = v.w;
            }
#pragma unroll
            for (int rr = 0; rr < 2; rr++) {
                int r = br + rr * 8;
                *(float4*)&Bs[r][bc] = *(const float4*)(Wg + (size_t)(kt + r) * HH + bc);
            }
            __syncthreads();
#pragma unroll
            for (int kk = 0; kk < 16; kk++) {
                float a[8], bfr[8];
                *(float4*)&a[0]   = *(float4*)&As[kk][ty * 4];
                *(float4*)&a[4]   = *(float4*)&As[kk][64 + ty * 4];
                *(float4*)&bfr[0] = *(float4*)&Bs[kk][tx * 4];
                *(float4*)&bfr[4] = *(float4*)&Bs[kk][64 + tx * 4];
#pragma unroll
                for (int i = 0; i < 8; i++)
#pragma unroll
                    for (int j = 0; j < 8; j++)
                        acc[i][j] = fmaf(a[i], bfr[j], acc[i][j]);
            }
            __syncthreads();
        }

        float* pbase = g_part + (size_t)ks * (BB * NGATE);
#pragma unroll
        for (int i = 0; i < 8; i++) {
            int m = (i < 4) ? (ty * 4 + i) : (64 + ty * 4 + (i - 4));
            float* cp = pbase + (size_t)m * NGATE + n0;
            *(float4*)(cp + tx * 4)      = make_float4(acc[i][0], acc[i][1], acc[i][2], acc[i][3]);
            *(float4*)(cp + 64 + tx * 4) = make_float4(acc[i][4], acc[i][5], acc[i][6], acc[i][7]);
        }

        grid_barrier();   // partials visible

        // ---- Fused activation: gates = xg[t][b] + bias + sum_s part[s][b] ----
        {
            const float* xgb = xg + ((size_t)t * BB + bown) * NGATE;
            const float* p0 = g_part + (size_t)bown * NGATE;
            const float* p1 = p0 + 1 * (size_t)(BB * NGATE);
            const float* p2 = p0 + 2 * (size_t)(BB * NGATE);
            const float* p3 = p0 + 3 * (size_t)(BB * NGATE);

            float gv[4][4];
#pragma unroll
            for (int gg = 0; gg < 4; gg++) {
                int n = (gg << 10) | hcol;
                float4 v  = *(const float4*)(xgb + n);
                float4 q0 = *(const float4*)(p0 + n);
                float4 q1 = *(const float4*)(p1 + n);
                float4 q2 = *(const float4*)(p2 + n);
                float4 q3 = *(const float4*)(p3 + n);
                gv[gg][0] = v.x + q0.x + q1.x + q2.x + q3.x;
                gv[gg][1] = v.y + q0.y + q1.y + q2.y + q3.y;
                gv[gg][2] = v.z + q0.z + q1.z + q2.z + q3.z;
                gv[gg][3] = v.w + q0.w + q1.w + q2.w + q3.w;
            }
            gv[0][0] += b0.x; gv[0][1] += b0.y; gv[0][2] += b0.z; gv[0][3] += b0.w;
            gv[1][0] += b1.x; gv[1][1] += b1.y; gv[1][2] += b1.z; gv[1][3] += b1.w;
            gv[2][0] += b2.x; gv[2][1] += b2.y; gv[2][2] += b2.z; gv[2][3] += b2.w;
            gv[3][0] += b3.x; gv[3][1] += b3.y; gv[3][2] += b3.z; gv[3][3] += b3.w;

            float hv[4];
            float* cr = (float*)&creg;
#pragma unroll
            for (int e = 0; e < 4; e++) {
                float ig = 1.f / (1.f + expf(-gv[0][e]));
                float fg = 1.f / (1.f + expf(-gv[1][e]));
                float og = 1.f / (1.f + expf(-gv[2][e]));
                float ug = tanhf(gv[3][e]);
                float c = fg * cr[e] + ig * ug;
                cr[e] = c;
                hv[e] = og * tanhf(c);
            }
            float4 hvec = make_float4(hv[0], hv[1], hv[2], hv[3]);
            if (t == TT - 1)
                *(float4*)(out + bown * HH + hcol) = hvec;
            else
                *(float4*)(g_h + bown * HH + hcol) = hvec;
        }

        grid_barrier();   // h visible before next GEMM
    }
}

// ---------------------------------------------------------------------------
// Launch. Inputs (metadata order): x[128,512,1024], adjacency (unused),
// Wx[4,1024,1024], Wh[4,1024,1024], b[4,1024]. Output: h [128,1024] f32.
// Graph: exactly 2 kernel nodes.
// ---------------------------------------------------------------------------
extern "C" void kernel_launch(void* const* d_in, const int* in_sizes, int n_in,
                              void* d_out, int out_size)
{
    const float* x    = (const float*)d_in[0];
    const float* Wx   = (const float*)d_in[2];
    const float* Wh   = (const float*)d_in[3];
    const float* bias = (const float*)d_in[4];
    float* out = (float*)d_out;

    float* xg;
    cudaGetSymbolAddress((void**)&xg, g_xg);

    gemm_xgates<<<dim3(32, 512), 256>>>(x, Wx, xg);
    lstm_recurrence<<<NCTA, 256>>>(Wh, xg, bias, out);
}

// round 3
// speedup vs baseline: 1.8904x; 1.8904x over previous
#include <cuda_runtime.h>
#include <math.h>
#include <stdint.h>

#define BB 128
#define TT 512
#define DD 1024
#define HH 1024
#define NGATE 4096   // 4*H
#define NCTA 128     // persistent grid size (<=148 SMs -> all co-resident)

// Scratch (static device globals — no runtime allocation).
__device__ float g_xg[(size_t)TT * BB * NGATE];        // [t][b][4H] input projections
__device__ float g_part[4 * BB * NGATE];               // split-K partials [ks][b][4H]
__device__ float g_h[BB * HH];                         // recurrent h
__device__ unsigned g_bar;                             // grid barrier counter (never reset)

__device__ __forceinline__ uint32_t f2tf32(float f)
{
    uint32_t u;
    asm("cvt.rna.tf32.f32 %0, %1;" : "=r"(u) : "f"(f));
    return u;
}

__device__ __forceinline__ void mma_tf32(float* d, const uint32_t* a, const uint32_t* b)
{
    asm volatile(
        "mma.sync.aligned.m16n8k8.row.col.f32.tf32.tf32.f32 "
        "{%0,%1,%2,%3},{%4,%5,%6,%7},{%8,%9},{%0,%1,%2,%3};"
        : "+f"(d[0]), "+f"(d[1]), "+f"(d[2]), "+f"(d[3])
        : "r"(a[0]), "r"(a[1]), "r"(a[2]), "r"(a[3]), "r"(b[0]), "r"(b[1]));
}

// ---------------------------------------------------------------------------
// GEMM1 (tf32 tensor): xg[t][b][n] = sum_k x[b][t][k] * Wx[g][k][h]
// Block tile 128(m=b) x 128(n) x 32(k). 8 warps as 2(m) x 4(n); warp tile
// 64x32 = 4x4 m16n8k8 mma tiles. grid = (32 n-tiles, 512 t).
// ---------------------------------------------------------------------------
__global__ __launch_bounds__(256) void gemm_xgates(
    const float* __restrict__ x, const float* __restrict__ Wx,
    float* __restrict__ out)
{
    __shared__ uint32_t As[32 * 132];   // [k][m], tf32 bits
    __shared__ uint32_t Bs[32 * 132];   // [k][n], tf32 bits

    const int tid  = threadIdx.x;
    const int lane = tid & 31;
    const int wid  = tid >> 5;
    const int gq   = lane >> 2;   // groupID 0..7
    const int cq   = lane & 3;    // threadID_in_group 0..3

    const int t  = blockIdx.y;
    const int n0 = blockIdx.x * 128;
    const int gg = n0 >> 10;
    const int hb = n0 & 1023;

    const int wm = wid >> 2;          // 0..1 -> m offset 64*wm
    const int wn = wid & 3;           // 0..3 -> n offset 32*wn
    const int m0w = wm * 64;
    const int n0w = wn * 32;

    float acc[4][4][4];
#pragma unroll
    for (int i = 0; i < 4; i++)
#pragma unroll
        for (int j = 0; j < 4; j++)
#pragma unroll
            for (int e = 0; e < 4; e++) acc[i][j][e] = 0.f;

    const float* Wg = Wx + (size_t)gg * DD * HH + hb;

    // A load mapping: m = tid>>1 (0..127), k offset (tid&1)*16, 4 float4
    const int am = tid >> 1;
    const int akq = (tid & 1) * 16;
    // B load mapping: k = tid>>3 (0..31), n offset (tid&7)*16, 4 float4
    const int bk = tid >> 3;
    const int bnq = (tid & 7) * 16;

    for (int kt = 0; kt < DD; kt += 32) {
        // load A tile [k32][m128]
        {
            const float* src = x + (size_t)am * (TT * DD) + (size_t)t * DD + kt + akq;
#pragma unroll
            for (int j = 0; j < 4; j++) {
                float4 v = *(const float4*)(src + j * 4);
                As[(akq + j * 4 + 0) * 132 + am] = f2tf32(v.x);
                As[(akq + j * 4 + 1) * 132 + am] = f2tf32(v.y);
                As[(akq + j * 4 + 2) * 132 + am] = f2tf32(v.z);
                As[(akq + j * 4 + 3) * 132 + am] = f2tf32(v.w);
            }
        }
        // load B tile [k32][n128]
        {
            const float* src = Wg + (size_t)(kt + bk) * HH + bnq;
#pragma unroll
            for (int j = 0; j < 4; j++) {
                float4 v = *(const float4*)(src + j * 4);
                Bs[bk * 132 + bnq + j * 4 + 0] = f2tf32(v.x);
                Bs[bk * 132 + bnq + j * 4 + 1] = f2tf32(v.y);
                Bs[bk * 132 + bnq + j * 4 + 2] = f2tf32(v.z);
                Bs[bk * 132 + bnq + j * 4 + 3] = f2tf32(v.w);
            }
        }
        __syncthreads();

#pragma unroll
        for (int kk = 0; kk < 4; kk++) {
            const int kb = kk * 8;
            uint32_t af[4][4], bf[4][2];
#pragma unroll
            for (int mt = 0; mt < 4; mt++) {
                int m = m0w + mt * 16 + gq;
                af[mt][0] = As[(kb + cq) * 132 + m];
                af[mt][1] = As[(kb + cq) * 132 + m + 8];
                af[mt][2] = As[(kb + cq + 4) * 132 + m];
                af[mt][3] = As[(kb + cq + 4) * 132 + m + 8];
            }
#pragma unroll
            for (int nt = 0; nt < 4; nt++) {
                int n = n0w + nt * 8 + gq;
                bf[nt][0] = Bs[(kb + cq) * 132 + n];
                bf[nt][1] = Bs[(kb + cq + 4) * 132 + n];
            }
#pragma unroll
            for (int mt = 0; mt < 4; mt++)
#pragma unroll
                for (int nt = 0; nt < 4; nt++)
                    mma_tf32(acc[mt][nt], af[mt], bf[nt]);
        }
        __syncthreads();
    }

    // store: d0(g,2c) d1(g,2c+1) d2(g+8,2c) d3(g+8,2c+1)
#pragma unroll
    for (int mt = 0; mt < 4; mt++) {
        int r0 = m0w + mt * 16 + gq;
#pragma unroll
        for (int nt = 0; nt < 4; nt++) {
            int cc = n0 + n0w + nt * 8 + 2 * cq;
            float* p0 = out + ((size_t)t * BB + r0) * NGATE + cc;
            float* p1 = out + ((size_t)t * BB + r0 + 8) * NGATE + cc;
            *(float2*)p0 = make_float2(acc[mt][nt][0], acc[mt][nt][1]);
            *(float2*)p1 = make_float2(acc[mt][nt][2], acc[mt][nt][3]);
        }
    }
}

// ---------------------------------------------------------------------------
// Grid barrier: stateless generation counter.
// ---------------------------------------------------------------------------
__device__ __forceinline__ void grid_barrier()
{
    __syncthreads();
    if (threadIdx.x == 0) {
        __threadfence();
        unsigned old = atomicAdd(&g_bar, 1u);
        unsigned target = (old / NCTA + 1u) * (unsigned)NCTA;
        while (atomicAdd(&g_bar, 0u) < target) { __nanosleep(32); }
        __threadfence();
    }
    __syncthreads();
}

// ---------------------------------------------------------------------------
// Persistent recurrence (tf32 tensor): 128 CTAs x 256 threads, 512 steps.
// CTA = (n-tile 0..31, k-split 0..3). Wh slice (256k x 128n, tf32) persists
// in dynamic smem for the whole kernel; per step only h chunks stream in.
// Activation: CTA b owns batch row b; c stays in registers.
// ---------------------------------------------------------------------------
extern __shared__ uint32_t dynsmem[];

__global__ __launch_bounds__(256) void lstm_recurrence(
    const float* __restrict__ Wh, const float* __restrict__ xg,
    const float* __restrict__ bias, float* __restrict__ out)
{
    uint32_t* BsW = dynsmem;               // [256][132] persistent Wh tile (tf32)
    uint32_t* AsH = dynsmem + 256 * 132;   // [32][132] streamed h tile (tf32)

    const int tid  = threadIdx.x;
    const int lane = tid & 31;
    const int wid  = tid >> 5;
    const int gq   = lane >> 2;
    const int cq   = lane & 3;

    const int nt = blockIdx.x & 31;
    const int ks = blockIdx.x >> 5;
    const int n0 = nt * 128;
    const int gg = n0 >> 10;
    const int hb = n0 & 1023;
    const int k0 = ks * 256;

    const int wm = wid >> 2;
    const int wn = wid & 3;
    const int m0w = wm * 64;
    const int n0w = wn * 32;

    const float* Wg = Wh + (size_t)gg * HH * HH + hb;

    // ---- preload Wh slice into smem (tf32), once ----
    for (int i = tid; i < 256 * 32; i += 256) {   // i indexes float4: 32 per row
        int kr = i >> 5;
        int nc = (i & 31) * 4;
        float4 v = *(const float4*)(Wg + (size_t)(k0 + kr) * HH + nc);
        BsW[kr * 132 + nc + 0] = f2tf32(v.x);
        BsW[kr * 132 + nc + 1] = f2tf32(v.y);
        BsW[kr * 132 + nc + 2] = f2tf32(v.z);
        BsW[kr * 132 + nc + 3] = f2tf32(v.w);
    }

    // Activation role: batch row b = blockIdx.x, cols tid*4..+3
    const int bown = blockIdx.x;
    const int hcol = tid * 4;
    float4 creg = make_float4(0.f, 0.f, 0.f, 0.f);
    float4 bb0 = *(const float4*)(bias + hcol);
    float4 bb1 = *(const float4*)(bias + 1024 + hcol);
    float4 bb2 = *(const float4*)(bias + 2048 + hcol);
    float4 bb3 = *(const float4*)(bias + 3072 + hcol);

    *(float4*)(g_h + bown * HH + hcol) = make_float4(0.f, 0.f, 0.f, 0.f);
    grid_barrier();

    const int am = tid >> 1;
    const int akq = (tid & 1) * 16;

    for (int t = 0; t < TT; t++) {
        float acc[4][4][4];
#pragma unroll
        for (int i = 0; i < 4; i++)
#pragma unroll
            for (int j = 0; j < 4; j++)
#pragma unroll
                for (int e = 0; e < 4; e++) acc[i][j][e] = 0.f;

        for (int kt = 0; kt < 8; kt++) {   // 8 chunks of k32
            // load h chunk [k32][m128]
            const float* src = g_h + (size_t)am * HH + k0 + kt * 32 + akq;
#pragma unroll
            for (int j = 0; j < 4; j++) {
                float4 v = *(const float4*)(src + j * 4);
                AsH[(akq + j * 4 + 0) * 132 + am] = f2tf32(v.x);
                AsH[(akq + j * 4 + 1) * 132 + am] = f2tf32(v.y);
                AsH[(akq + j * 4 + 2) * 132 + am] = f2tf32(v.z);
                AsH[(akq + j * 4 + 3) * 132 + am] = f2tf32(v.w);
            }
            __syncthreads();

#pragma unroll
            for (int kk = 0; kk < 4; kk++) {
                const int kb = kk * 8;
                const int kw = kt * 32 + kb;
                uint32_t af[4][4], bf[4][2];
#pragma unroll
                for (int mt = 0; mt < 4; mt++) {
                    int m = m0w + mt * 16 + gq;
                    af[mt][0] = AsH[(kb + cq) * 132 + m];
                    af[mt][1] = AsH[(kb + cq) * 132 + m + 8];
                    af[mt][2] = AsH[(kb + cq + 4) * 132 + m];
                    af[mt][3] = AsH[(kb + cq + 4) * 132 + m + 8];
                }
#pragma unroll
                for (int nt2 = 0; nt2 < 4; nt2++) {
                    int n = n0w + nt2 * 8 + gq;
                    bf[nt2][0] = BsW[(kw + cq) * 132 + n];
                    bf[nt2][1] = BsW[(kw + cq + 4) * 132 + n];
                }
#pragma unroll
                for (int mt = 0; mt < 4; mt++)
#pragma unroll
                    for (int nt2 = 0; nt2 < 4; nt2++)
                        mma_tf32(acc[mt][nt2], af[mt], bf[nt2]);
            }
            __syncthreads();
        }

        // store partials
        float* pbase = g_part + (size_t)ks * (BB * NGATE);
#pragma unroll
        for (int mt = 0; mt < 4; mt++) {
            int r0 = m0w + mt * 16 + gq;
#pragma unroll
            for (int nt2 = 0; nt2 < 4; nt2++) {
                int cc = n0 + n0w + nt2 * 8 + 2 * cq;
                *(float2*)(pbase + (size_t)r0 * NGATE + cc) =
                    make_float2(acc[mt][nt2][0], acc[mt][nt2][1]);
                *(float2*)(pbase + (size_t)(r0 + 8) * NGATE + cc) =
                    make_float2(acc[mt][nt2][2], acc[mt][nt2][3]);
            }
        }

        grid_barrier();   // partials visible

        // ---- fused activation ----
        {
            const float* xgb = xg + ((size_t)t * BB + bown) * NGATE;
            const float* p0 = g_part + (size_t)bown * NGATE;
            const float* p1 = p0 + 1 * (size_t)(BB * NGATE);
            const float* p2 = p0 + 2 * (size_t)(BB * NGATE);
            const float* p3 = p0 + 3 * (size_t)(BB * NGATE);

            float gv[4][4];
#pragma unroll
            for (int gi = 0; gi < 4; gi++) {
                int n = (gi << 10) | hcol;
                float4 v  = *(const float4*)(xgb + n);
                float4 q0 = *(const float4*)(p0 + n);
                float4 q1 = *(const float4*)(p1 + n);
                float4 q2 = *(const float4*)(p2 + n);
                float4 q3 = *(const float4*)(p3 + n);
                gv[gi][0] = v.x + q0.x + q1.x + q2.x + q3.x;
                gv[gi][1] = v.y + q0.y + q1.y + q2.y + q3.y;
                gv[gi][2] = v.z + q0.z + q1.z + q2.z + q3.z;
                gv[gi][3] = v.w + q0.w + q1.w + q2.w + q3.w;
            }
            gv[0][0] += bb0.x; gv[0][1] += bb0.y; gv[0][2] += bb0.z; gv[0][3] += bb0.w;
            gv[1][0] += bb1.x; gv[1][1] += bb1.y; gv[1][2] += bb1.z; gv[1][3] += bb1.w;
            gv[2][0] += bb2.x; gv[2][1] += bb2.y; gv[2][2] += bb2.z; gv[2][3] += bb2.w;
            gv[3][0] += bb3.x; gv[3][1] += bb3.y; gv[3][2] += bb3.z; gv[3][3] += bb3.w;

            float hv[4];
            float* cr = (float*)&creg;
#pragma unroll
            for (int e = 0; e < 4; e++) {
                float ig = 1.f / (1.f + expf(-gv[0][e]));
                float fg = 1.f / (1.f + expf(-gv[1][e]));
                float og = 1.f / (1.f + expf(-gv[2][e]));
                float ug = tanhf(gv[3][e]);
                float c = fg * cr[e] + ig * ug;
                cr[e] = c;
                hv[e] = og * tanhf(c);
            }
            float4 hvec = make_float4(hv[0], hv[1], hv[2], hv[3]);
            if (t == TT - 1)
                *(float4*)(out + bown * HH + hcol) = hvec;
            else
                *(float4*)(g_h + bown * HH + hcol) = hvec;
        }

        grid_barrier();   // h visible before next GEMM
    }
}

// ---------------------------------------------------------------------------
// Launch. Inputs: x[128,512,1024], adjacency (unused), Wx[4,1024,1024],
// Wh[4,1024,1024], b[4,1024]. Output: h [128,1024] f32. Graph: 2 nodes.
// ---------------------------------------------------------------------------
extern "C" void kernel_launch(void* const* d_in, const int* in_sizes, int n_in,
                              void* d_out, int out_size)
{
    const float* x    = (const float*)d_in[0];
    const float* Wx   = (const float*)d_in[2];
    const float* Wh   = (const float*)d_in[3];
    const float* bias = (const float*)d_in[4];
    float* out = (float*)d_out;

    float* xg;
    cudaGetSymbolAddress((void**)&xg, g_xg);

    const int rec_smem = (256 * 132 + 32 * 132) * 4;   // 152064 B
    static int configured = 0;
    if (!configured) {
        cudaFuncSetAttribute(lstm_recurrence,
                             cudaFuncAttributeMaxDynamicSharedMemorySize, rec_smem);
        configured = 1;
    }

    gemm_xgates<<<dim3(32, 512), 256>>>(x, Wx, xg);
    lstm_recurrence<<<NCTA, 256, rec_smem>>>(Wh, xg, bias, out);
}